// round 3
// baseline (speedup 1.0000x reference)
#include <cuda_runtime.h>

#define TT 1024
#define DD 263

// group id per joint: 0=ROOT_AND_SPINE(n=6), 1=FEET(n=4), 2=HANDS(n=8), 3=OTHER(n=4)
__constant__ int c_grp[22] = {0,3,3,0,3,3,0,1,1,0,1,1,0,2,2,0,2,2,2,2,2,2};

__device__ __forceinline__ float blockReduceMax(float v, float* s_red) {
    int t = threadIdx.x;
    #pragma unroll
    for (int o = 16; o > 0; o >>= 1) v = fmaxf(v, __shfl_xor_sync(0xffffffffu, v, o));
    if ((t & 31) == 0) s_red[t >> 5] = v;
    __syncthreads();
    if (t < 32) {
        float w = s_red[t];
        #pragma unroll
        for (int o = 16; o > 0; o >>= 1) w = fmaxf(w, __shfl_xor_sync(0xffffffffu, w, o));
        if (t == 0) s_red[0] = w;
    }
    __syncthreads();
    float r = s_red[0];
    __syncthreads();
    return r;
}

__device__ __forceinline__ float blockReduceSumF(float v, float* s_red) {
    int t = threadIdx.x;
    #pragma unroll
    for (int o = 16; o > 0; o >>= 1) v += __shfl_xor_sync(0xffffffffu, v, o);
    if ((t & 31) == 0) s_red[t >> 5] = v;
    __syncthreads();
    if (t < 32) {
        float w = s_red[t];
        #pragma unroll
        for (int o = 16; o > 0; o >>= 1) w += __shfl_xor_sync(0xffffffffu, w, o);
        if (t == 0) s_red[0] = w;
    }
    __syncthreads();
    float r = s_red[0];
    __syncthreads();
    return r;
}

__device__ __forceinline__ int blockReduceSumI(int v, int* s_red) {
    int t = threadIdx.x;
    #pragma unroll
    for (int o = 16; o > 0; o >>= 1) v += __shfl_xor_sync(0xffffffffu, v, o);
    if ((t & 31) == 0) s_red[t >> 5] = v;
    __syncthreads();
    if (t < 32) {
        int w = s_red[t];
        #pragma unroll
        for (int o = 16; o > 0; o >>= 1) w += __shfl_xor_sync(0xffffffffu, w, o);
        if (t == 0) s_red[0] = w;
    }
    __syncthreads();
    int r = s_red[0];
    __syncthreads();
    return r;
}

__global__ __launch_bounds__(1024, 1)
void msal_kernel(const float* __restrict__ motion,
                 const int* __restrict__ mask,      // bool delivered as int32 by harness
                 float* __restrict__ out,
                 int Bn)
{
    __shared__ float s_rx[TT], s_rz[TT];
    __shared__ float s_px[2][TT], s_py[2][TT], s_pz[2][TT];  // double-buffered joint staging
    __shared__ float s_sal[TT];
    __shared__ float s_sort[TT];
    __shared__ float s_redf[32];
    __shared__ int   s_redi[32];

    const int t = threadIdx.x;
    const int b = blockIdx.x;
    const float* row = motion + ((long)b * TT + t) * DD;
    const int mv = mask[(long)b * TT + t];
    const float maskf = mv ? 1.0f : 0.0f;

    // ---- ang = exclusive cumsum of rot_vel (sequential order to match reference) ----
    s_px[0][t] = row[0];
    __syncthreads();
    if (t == 0) {
        float a = 0.0f;
        for (int i = 0; i < TT; i++) { s_py[0][i] = a; a += s_px[0][i]; }
    }
    __syncthreads();
    const float ang = s_py[0][t];
    const float qc = cosf(ang);
    const float qs = sinf(ang);

    // ---- root xz step vectors rotated by qinv(quat), then inclusive cumsum ----
    float vx = 0.0f, vz = 0.0f;
    if (t > 0) { vx = row[1 - DD]; vz = row[2 - DD]; }
    {
        // qvec = (0, -s, 0); uv = cross(qvec, v); uuv = cross(qvec, uv)
        float uvx = (-qs) * vz;
        float uvz = qs * vx;
        float uuvx = (-qs) * uvz;
        float uuvz = qs * uvx;
        s_rx[t] = vx + 2.0f * (qc * uvx + uuvx);
        s_rz[t] = vz + 2.0f * (qc * uvz + uuvz);
    }
    __syncthreads();
    if (t == 0)  { float a = 0.0f; for (int i = 0; i < TT; i++) { a += s_rx[i]; s_rx[i] = a; } }
    if (t == 32) { float a = 0.0f; for (int i = 0; i < TT; i++) { a += s_rz[i]; s_rz[i] = a; } }
    __syncthreads();
    const float rx = s_rx[t];
    const float rz = s_rz[t];

    // ---- group energies: loop joints, stage positions of all t in smem ----
    float sv0 = 0.f, sa0 = 0.f, sj0 = 0.f;
    float sv1 = 0.f, sa1 = 0.f, sj1 = 0.f;
    float sv2 = 0.f, sa2 = 0.f, sj2 = 0.f;
    float sv3 = 0.f, sa3 = 0.f, sj3 = 0.f;

    for (int j = 0; j < 22; j++) {
        const int buf = j & 1;
        float px, py, pz;
        if (j == 0) {
            px = rx; py = row[3]; pz = rz;
        } else {
            const int o = 4 + 3 * (j - 1);
            const float wx = row[o], wy = row[o + 1], wz = row[o + 2];
            float uvx = (-qs) * wz;
            float uvz = qs * wx;
            float uuvx = (-qs) * uvz;
            float uuvz = qs * uvx;
            float rxx = wx + 2.0f * (qc * uvx + uuvx);
            float rzz = wz + 2.0f * (qc * uvz + uuvz);
            px = rxx + rx; py = wy; pz = rzz + rz;
        }
        s_px[buf][t] = px; s_py[buf][t] = py; s_pz[buf][t] = pz;
        __syncthreads();   // writes visible; previous iteration used the other buffer

        float p2x = 0.f, p2y = 0.f, p2z = 0.f;
        float p1x = 0.f, p1y = 0.f, p1z = 0.f;
        float p0x = 0.f, p0y = 0.f, p0z = 0.f;
        if (t >= 1) { p2x = s_px[buf][t-1]; p2y = s_py[buf][t-1]; p2z = s_pz[buf][t-1]; }
        if (t >= 2) { p1x = s_px[buf][t-2]; p1y = s_py[buf][t-2]; p1z = s_pz[buf][t-2]; }
        if (t >= 3) { p0x = s_px[buf][t-3]; p0y = s_py[buf][t-3]; p0z = s_pz[buf][t-3]; }

        // vel[t], vel[t-1], vel[t-2] with prepend semantics (vel[0]=0)
        float v3x = (t >= 1) ? px - p2x : 0.f, v3y = (t >= 1) ? py - p2y : 0.f, v3z = (t >= 1) ? pz - p2z : 0.f;
        float v2x = (t >= 2) ? p2x - p1x : 0.f, v2y = (t >= 2) ? p2y - p1y : 0.f, v2z = (t >= 2) ? p2z - p1z : 0.f;
        float v1x = (t >= 3) ? p1x - p0x : 0.f, v1y = (t >= 3) ? p1y - p0y : 0.f, v1z = (t >= 3) ? p1z - p0z : 0.f;
        float a3x = (t >= 1) ? v3x - v2x : 0.f, a3y = (t >= 1) ? v3y - v2y : 0.f, a3z = (t >= 1) ? v3z - v2z : 0.f;
        float a2x = (t >= 2) ? v2x - v1x : 0.f, a2y = (t >= 2) ? v2y - v1y : 0.f, a2z = (t >= 2) ? v2z - v1z : 0.f;
        float jx  = (t >= 1) ? a3x - a2x : 0.f, jy  = (t >= 1) ? a3y - a2y : 0.f, jz  = (t >= 1) ? a3z - a2z : 0.f;

        float nv = sqrtf(((v3x * v3x + v3y * v3y) + v3z * v3z) + 1e-12f);
        float na = sqrtf(((a3x * a3x + a3y * a3y) + a3z * a3z) + 1e-12f);
        float nj = sqrtf(((jx * jx + jy * jy) + jz * jz) + 1e-12f);

        int g = c_grp[j];
        if      (g == 0) { sv0 += nv; sa0 += na; sj0 += nj; }
        else if (g == 1) { sv1 += nv; sa1 += na; sj1 += nj; }
        else if (g == 2) { sv2 += nv; sa2 += na; sj2 += nj; }
        else             { sv3 += nv; sa3 += na; sj3 += nj; }
    }

    float E0 = ((sv0 / 6.0f) + 0.6f * (sa0 / 6.0f)) + 0.35f * (sj0 / 6.0f);
    float E1 = ((sv1 / 4.0f) + 0.6f * (sa1 / 4.0f)) + 0.35f * (sj1 / 4.0f);
    float E2 = ((sv2 / 8.0f) + 0.6f * (sa2 / 8.0f)) + 0.35f * (sj2 / 8.0f);
    float E3 = ((sv3 / 4.0f) + 0.6f * (sa3 / 4.0f)) + 0.35f * (sj3 / 4.0f);

    // ---- turning ----
    float pvx = 0.f, pvz = 0.f;
    if (t >= 1) { pvx = rx - s_rx[t - 1]; pvz = rz - s_rz[t - 1]; }
    bool z1 = (fabsf(pvx) < 1e-8f) && (fabsf(pvz) < 1e-8f);
    float h1 = atan2f(z1 ? 0.f : pvz, z1 ? 1.f : pvx);
    float h0 = 0.f;
    if (t >= 2) {
        float qx = s_rx[t - 1] - s_rx[t - 2];
        float qz = s_rz[t - 1] - s_rz[t - 2];
        bool z0 = (fabsf(qx) < 1e-8f) && (fabsf(qz) < 1e-8f);
        h0 = atan2f(z0 ? 0.f : qz, z0 ? 1.f : qx);
    }
    float hd = (t >= 1) ? h1 - h0 : 0.f;
    float wr = atan2f(sinf(hd), cosf(hd));
    float turn = fabsf(wr) * sqrtf((pvx * pvx + pvz * pvz) + 1e-12f);

    float sal = ((((1.6f * E0 + 1.4f * E1) + 1.2f * E2) + 0.8f * E3) + 1.6f * turn);
    sal *= maskf;

    // ---- normalize by row max ----
    float m = blockReduceMax(sal, s_redf);
    m = fmaxf(m, 1e-6f);
    float salN = fminf(fmaxf(sal / m, 0.0f), 1.0f) * maskf;
    s_sal[t] = salN;
    __syncthreads();

    // ---- local max suppression (window 5, pad 2) ----
    float lm = salN;
    #pragma unroll
    for (int d = -2; d <= 2; d++) {
        int i = t + d;
        if (i >= 0 && i < TT) lm = fmaxf(lm, s_sal[i]);
    }
    float keep = (salN >= lm - 1e-6f) ? 1.0f : 0.0f;
    float probs = salN * keep * maskf;
    probs = fminf(fmaxf(probs, 0.0f), 1.0f) * maskf;

    // ---- adaptive ST ----
    int n = blockReduceSumI(mv ? 1 : 0, s_redi);
    float hv = (n > 0) ? 1.0f : 0.0f;
    int last = ((n > 1) ? n : 1) - 1;
    float ep = (t == 0 || t == last) ? hv : 0.0f;
    probs = fmaxf(probs, ep) * maskf;

    float nf = (float)((n > 1) ? n : 1);
    float asum = blockReduceSumF(probs * maskf, s_redf);
    float activity = asum / nf;
    float q = 0.85f + 0.1f * 0.5f - 0.1f * activity;
    q = fminf(fmaxf(q, 0.8f), 0.95f);
    float pos = q * (nf - 1.0f);
    float lof = floorf(pos), hif = ceilf(pos);
    int ilo = (int)lof, ihi = (int)hif;

    // ---- bitonic sort of masked probs (ascending) ----
    s_sort[t] = mv ? probs : 2.0f;
    __syncthreads();
    for (int k = 2; k <= TT; k <<= 1) {
        for (int j2 = k >> 1; j2 > 0; j2 >>= 1) {
            int ixj = t ^ j2;
            if (ixj > t) {
                float a = s_sort[t], bb = s_sort[ixj];
                bool asc = (t & k) == 0;
                if ((a > bb) == asc) { s_sort[t] = bb; s_sort[ixj] = a; }
            }
            __syncthreads();
        }
    }
    float vlo = s_sort[ilo], vhi = s_sort[ihi];
    float cut = vlo + (pos - lof) * (vhi - vlo);

    float hard;
    if (n > 0 && n <= 2)      hard = maskf;
    else if (n > 2)           hard = (probs >= cut) ? 1.0f : 0.0f;
    else                      hard = 0.0f;

    hard = fmaxf(hard, ep) * maskf;
    float probsF = fmaxf(probs, ep) * maskf;
    float st = ((hard + probsF) - probsF) * maskf;   // literal straight-through arithmetic

    out[(long)b * TT + t] = probsF;
    out[(long)Bn * TT + (long)b * TT + t] = st;
}

extern "C" void kernel_launch(void* const* d_in, const int* in_sizes, int n_in,
                              void* d_out, int out_size) {
    const float* motion = (const float*)d_in[0];
    const int* mask = (const int*)d_in[1];
    float* out = (float*)d_out;
    int Bn = in_sizes[0] / (TT * DD);
    msal_kernel<<<Bn, TT>>>(motion, mask, out, Bn);
}

// round 5
// speedup vs baseline: 1.5221x; 1.5221x over previous
#include <cuda_runtime.h>

#define TT 1024
#define DD 263

// group id per joint: 0=ROOT_AND_SPINE(n=6), 1=FEET(n=4), 2=HANDS(n=8), 3=OTHER(n=4)
__constant__ int c_grp[22] = {0,3,3,0,3,3,0,1,1,0,1,1,0,2,2,0,2,2,2,2,2,2};

__device__ __forceinline__ float warpInclScan(float v) {
    int lane = threadIdx.x & 31;
    #pragma unroll
    for (int o = 1; o < 32; o <<= 1) {
        float n = __shfl_up_sync(0xffffffffu, v, o);
        if (lane >= o) v += n;
    }
    return v;
}

// inclusive block scan of one value (s_w: 32 floats)
__device__ __forceinline__ float blockInclScan(float v, float* s_w) {
    int lane = threadIdx.x & 31, wid = threadIdx.x >> 5;
    float x = warpInclScan(v);
    if (lane == 31) s_w[wid] = x;
    __syncthreads();
    if (wid == 0) { float y = s_w[lane]; y = warpInclScan(y); s_w[lane] = y; }
    __syncthreads();
    float off = (wid > 0) ? s_w[wid - 1] : 0.0f;
    return x + off;
}

// inclusive block scan of two values sharing barriers
__device__ __forceinline__ void blockInclScan2(float& a, float& b, float* swa, float* swb) {
    int lane = threadIdx.x & 31, wid = threadIdx.x >> 5;
    float xa = warpInclScan(a), xb = warpInclScan(b);
    if (lane == 31) { swa[wid] = xa; swb[wid] = xb; }
    __syncthreads();
    if (wid == 0) {
        float ya = swa[lane], yb = swb[lane];
        ya = warpInclScan(ya); yb = warpInclScan(yb);
        swa[lane] = ya; swb[lane] = yb;
    }
    __syncthreads();
    a = xa + ((wid > 0) ? swa[wid - 1] : 0.0f);
    b = xb + ((wid > 0) ? swb[wid - 1] : 0.0f);
}

__device__ __forceinline__ float blockReduceMax(float v, float* s_red) {
    int t = threadIdx.x;
    #pragma unroll
    for (int o = 16; o > 0; o >>= 1) v = fmaxf(v, __shfl_xor_sync(0xffffffffu, v, o));
    if ((t & 31) == 0) s_red[t >> 5] = v;
    __syncthreads();
    if (t < 32) {
        float w = s_red[t];
        #pragma unroll
        for (int o = 16; o > 0; o >>= 1) w = fmaxf(w, __shfl_xor_sync(0xffffffffu, w, o));
        if (t == 0) s_red[0] = w;
    }
    __syncthreads();
    float r = s_red[0];
    __syncthreads();
    return r;
}

__device__ __forceinline__ float blockReduceSumF(float v, float* s_red) {
    int t = threadIdx.x;
    #pragma unroll
    for (int o = 16; o > 0; o >>= 1) v += __shfl_xor_sync(0xffffffffu, v, o);
    if ((t & 31) == 0) s_red[t >> 5] = v;
    __syncthreads();
    if (t < 32) {
        float w = s_red[t];
        #pragma unroll
        for (int o = 16; o > 0; o >>= 1) w += __shfl_xor_sync(0xffffffffu, w, o);
        if (t == 0) s_red[0] = w;
    }
    __syncthreads();
    float r = s_red[0];
    __syncthreads();
    return r;
}

__device__ __forceinline__ int blockReduceSumI(int v, int* s_red) {
    int t = threadIdx.x;
    #pragma unroll
    for (int o = 16; o > 0; o >>= 1) v += __shfl_xor_sync(0xffffffffu, v, o);
    if ((t & 31) == 0) s_red[t >> 5] = v;
    __syncthreads();
    if (t < 32) {
        int w = s_red[t];
        #pragma unroll
        for (int o = 16; o > 0; o >>= 1) w += __shfl_xor_sync(0xffffffffu, w, o);
        if (t == 0) s_red[0] = w;
    }
    __syncthreads();
    int r = s_red[0];
    __syncthreads();
    return r;
}

__global__ __launch_bounds__(1024, 1)
void msal_kernel(const float* __restrict__ motion,
                 const int* __restrict__ mask,      // bool delivered as int32 by harness
                 float* __restrict__ out,
                 int Bn)
{
    __shared__ float s_rx[TT], s_rz[TT];
    __shared__ float s_px[2][TT], s_py[2][TT], s_pz[2][TT];  // double-buffered joint staging
    __shared__ float s_sal[TT];
    __shared__ float s_srt[2][TT];                            // double-buffered sort
    __shared__ float s_redf[32];
    __shared__ int   s_redi[32];
    __shared__ float s_w1[32], s_w2[32];

    const int t = threadIdx.x;
    const int b = blockIdx.x;
    const float* row = motion + ((long)b * TT + t) * DD;
    const int mv = mask[(long)b * TT + t];
    const float maskf = mv ? 1.0f : 0.0f;

    // ---- ang = exclusive cumsum of rot_vel (parallel scan) ----
    const float rv = row[0];
    const float ang = blockInclScan(rv, s_w1) - rv;   // exclusive; t=0 gives exact 0
    const float qc = cosf(ang);
    const float qs = sinf(ang);

    // ---- root xz step vectors rotated by qinv(quat), then inclusive cumsum ----
    float vx = 0.0f, vz = 0.0f;
    if (t > 0) { vx = row[1 - DD]; vz = row[2 - DD]; }
    float rxv, rzv;
    {
        // qvec = (0, -s, 0); uv = cross(qvec, v); uuv = cross(qvec, uv)
        float uvx = (-qs) * vz;
        float uvz = qs * vx;
        float uuvx = (-qs) * uvz;
        float uuvz = qs * uvx;
        rxv = vx + 2.0f * (qc * uvx + uuvx);
        rzv = vz + 2.0f * (qc * uvz + uuvz);
    }
    __syncthreads();    // protect s_w reuse inside scan2
    blockInclScan2(rxv, rzv, s_w1, s_w2);
    const float rx = rxv;
    const float rz = rzv;
    s_rx[t] = rx; s_rz[t] = rz;
    // (barrier below, before first neighbor read, covers s_rx/s_rz visibility)

    // ---- group energies: loop joints, stage positions in smem, prefetch next joint ----
    float sv0 = 0.f, sa0 = 0.f, sj0 = 0.f;
    float sv1 = 0.f, sa1 = 0.f, sj1 = 0.f;
    float sv2 = 0.f, sa2 = 0.f, sj2 = 0.f;
    float sv3 = 0.f, sa3 = 0.f, sj3 = 0.f;

    float wx = 0.f, wy = 0.f, wz = 0.f;   // data for current joint j (valid for j>=1)

    for (int j = 0; j < 22; j++) {
        const int buf = j & 1;
        float px, py, pz;
        if (j == 0) {
            px = rx; py = row[3]; pz = rz;
        } else {
            float uvx = (-qs) * wz;
            float uvz = qs * wx;
            float uuvx = (-qs) * uvz;
            float uuvz = qs * uvx;
            float rxx = wx + 2.0f * (qc * uvx + uuvx);
            float rzz = wz + 2.0f * (qc * uvz + uuvz);
            px = rxx + rx; py = wy; pz = rzz + rz;
        }
        // prefetch next joint's raw data; latency hides behind barrier + consume
        float nx = 0.f, ny = 0.f, nz = 0.f;
        if (j < 21) {
            const int o = 4 + 3 * j;       // offsets for joint (j+1): joints idx j in data
            nx = row[o]; ny = row[o + 1]; nz = row[o + 2];
        }
        s_px[buf][t] = px; s_py[buf][t] = py; s_pz[buf][t] = pz;
        __syncthreads();   // writes visible; previous iteration used the other buffer

        float p2x = 0.f, p2y = 0.f, p2z = 0.f;
        float p1x = 0.f, p1y = 0.f, p1z = 0.f;
        float p0x = 0.f, p0y = 0.f, p0z = 0.f;
        if (t >= 1) { p2x = s_px[buf][t-1]; p2y = s_py[buf][t-1]; p2z = s_pz[buf][t-1]; }
        if (t >= 2) { p1x = s_px[buf][t-2]; p1y = s_py[buf][t-2]; p1z = s_pz[buf][t-2]; }
        if (t >= 3) { p0x = s_px[buf][t-3]; p0y = s_py[buf][t-3]; p0z = s_pz[buf][t-3]; }

        // vel[t], vel[t-1], vel[t-2] with prepend semantics (vel[0]=0)
        float v3x = (t >= 1) ? px - p2x : 0.f, v3y = (t >= 1) ? py - p2y : 0.f, v3z = (t >= 1) ? pz - p2z : 0.f;
        float v2x = (t >= 2) ? p2x - p1x : 0.f, v2y = (t >= 2) ? p2y - p1y : 0.f, v2z = (t >= 2) ? p2z - p1z : 0.f;
        float v1x = (t >= 3) ? p1x - p0x : 0.f, v1y = (t >= 3) ? p1y - p0y : 0.f, v1z = (t >= 3) ? p1z - p0z : 0.f;
        float a3x = (t >= 1) ? v3x - v2x : 0.f, a3y = (t >= 1) ? v3y - v2y : 0.f, a3z = (t >= 1) ? v3z - v2z : 0.f;
        float a2x = (t >= 2) ? v2x - v1x : 0.f, a2y = (t >= 2) ? v2y - v1y : 0.f, a2z = (t >= 2) ? v2z - v1z : 0.f;
        float jx  = (t >= 1) ? a3x - a2x : 0.f, jy  = (t >= 1) ? a3y - a2y : 0.f, jz  = (t >= 1) ? a3z - a2z : 0.f;

        float nv = sqrtf(((v3x * v3x + v3y * v3y) + v3z * v3z) + 1e-12f);
        float na = sqrtf(((a3x * a3x + a3y * a3y) + a3z * a3z) + 1e-12f);
        float nj = sqrtf(((jx * jx + jy * jy) + jz * jz) + 1e-12f);

        int g = c_grp[j];
        if      (g == 0) { sv0 += nv; sa0 += na; sj0 += nj; }
        else if (g == 1) { sv1 += nv; sa1 += na; sj1 += nj; }
        else if (g == 2) { sv2 += nv; sa2 += na; sj2 += nj; }
        else             { sv3 += nv; sa3 += na; sj3 += nj; }

        wx = nx; wy = ny; wz = nz;
    }

    float E0 = ((sv0 / 6.0f) + 0.6f * (sa0 / 6.0f)) + 0.35f * (sj0 / 6.0f);
    float E1 = ((sv1 / 4.0f) + 0.6f * (sa1 / 4.0f)) + 0.35f * (sj1 / 4.0f);
    float E2 = ((sv2 / 8.0f) + 0.6f * (sa2 / 8.0f)) + 0.35f * (sj2 / 8.0f);
    float E3 = ((sv3 / 4.0f) + 0.6f * (sa3 / 4.0f)) + 0.35f * (sj3 / 4.0f);

    // ---- turning ----
    float pvx = 0.f, pvz = 0.f;
    if (t >= 1) { pvx = rx - s_rx[t - 1]; pvz = rz - s_rz[t - 1]; }
    bool z1 = (fabsf(pvx) < 1e-8f) && (fabsf(pvz) < 1e-8f);
    float h1 = atan2f(z1 ? 0.f : pvz, z1 ? 1.f : pvx);
    float h0 = 0.f;
    if (t >= 2) {
        float qx = s_rx[t - 1] - s_rx[t - 2];
        float qz = s_rz[t - 1] - s_rz[t - 2];
        bool z0 = (fabsf(qx) < 1e-8f) && (fabsf(qz) < 1e-8f);
        h0 = atan2f(z0 ? 0.f : qz, z0 ? 1.f : qx);
    }
    float hd = (t >= 1) ? h1 - h0 : 0.f;
    float wr = atan2f(sinf(hd), cosf(hd));
    float turn = fabsf(wr) * sqrtf((pvx * pvx + pvz * pvz) + 1e-12f);

    float sal = ((((1.6f * E0 + 1.4f * E1) + 1.2f * E2) + 0.8f * E3) + 1.6f * turn);
    sal *= maskf;

    // ---- normalize by row max ----
    float m = blockReduceMax(sal, s_redf);
    m = fmaxf(m, 1e-6f);
    float salN = fminf(fmaxf(sal / m, 0.0f), 1.0f) * maskf;
    s_sal[t] = salN;
    __syncthreads();

    // ---- local max suppression (window 5, pad 2) ----
    float lm = salN;
    #pragma unroll
    for (int d = -2; d <= 2; d++) {
        int i = t + d;
        if (i >= 0 && i < TT) lm = fmaxf(lm, s_sal[i]);
    }
    float keep = (salN >= lm - 1e-6f) ? 1.0f : 0.0f;
    float probs = salN * keep * maskf;
    probs = fminf(fmaxf(probs, 0.0f), 1.0f) * maskf;

    // ---- adaptive ST ----
    int n = blockReduceSumI(mv ? 1 : 0, s_redi);
    float hv = (n > 0) ? 1.0f : 0.0f;
    int last = ((n > 1) ? n : 1) - 1;
    float ep = (t == 0 || t == last) ? hv : 0.0f;
    probs = fmaxf(probs, ep) * maskf;

    float nf = (float)((n > 1) ? n : 1);
    float asum = blockReduceSumF(probs * maskf, s_redf);
    float activity = asum / nf;
    float q = 0.85f + 0.1f * 0.5f - 0.1f * activity;
    q = fminf(fmaxf(q, 0.8f), 0.95f);
    float pos = q * (nf - 1.0f);
    float lof = floorf(pos), hif = ceilf(pos);
    int ilo = (int)lof, ihi = (int)hif;

    // ---- hybrid bitonic sort (register value; shfl for j2<32, smem for j2>=32) ----
    float v = mv ? probs : 2.0f;
    int pbuf = 0;
    for (int k = 2; k <= TT; k <<= 1) {
        bool up = ((t & k) == 0);
        for (int j2 = k >> 1; j2 > 0; j2 >>= 1) {
            bool lower = ((t & j2) == 0);
            float p;
            if (j2 >= 32) {
                s_srt[pbuf][t] = v;
                __syncthreads();
                p = s_srt[pbuf][t ^ j2];
                pbuf ^= 1;
            } else {
                p = __shfl_xor_sync(0xffffffffu, v, j2);
            }
            float mn = fminf(v, p), mx = fmaxf(v, p);
            v = (lower == up) ? mn : mx;
        }
    }
    s_srt[pbuf][t] = v;
    __syncthreads();
    float vlo = s_srt[pbuf][ilo], vhi = s_srt[pbuf][ihi];
    float cut = vlo + (pos - lof) * (vhi - vlo);

    float hard;
    if (n > 0 && n <= 2)      hard = maskf;
    else if (n > 2)           hard = (probs >= cut) ? 1.0f : 0.0f;
    else                      hard = 0.0f;

    hard = fmaxf(hard, ep) * maskf;
    float probsF = fmaxf(probs, ep) * maskf;
    float st = ((hard + probsF) - probsF) * maskf;   // literal straight-through arithmetic

    out[(long)b * TT + t] = probsF;
    out[(long)Bn * TT + (long)b * TT + t] = st;
}

extern "C" void kernel_launch(void* const* d_in, const int* in_sizes, int n_in,
                              void* d_out, int out_size) {
    const float* motion = (const float*)d_in[0];
    const int* mask = (const int*)d_in[1];
    float* out = (float*)d_out;
    int Bn = in_sizes[0] / (TT * DD);
    msal_kernel<<<Bn, TT>>>(motion, mask, out, Bn);
}

// round 6
// speedup vs baseline: 2.0004x; 1.3143x over previous
#include <cuda_runtime.h>

#define TT 1024
#define NT 512
#define DD 263

// group id per joint: 0=ROOT_AND_SPINE(n=6), 1=FEET(n=4), 2=HANDS(n=8), 3=OTHER(n=4)
__constant__ int c_grp[22] = {0,3,3,0,3,3,0,1,1,0,1,1,0,2,2,0,2,2,2,2,2,2};

__device__ __forceinline__ float warpInclScan(float v) {
    int lane = threadIdx.x & 31;
    #pragma unroll
    for (int o = 1; o < 32; o <<= 1) {
        float n = __shfl_up_sync(0xffffffffu, v, o);
        if (lane >= o) v += n;
    }
    return v;
}

// inclusive block scan over 512 threads (16 warps); s_w: 32 floats
__device__ __forceinline__ float blockInclScan(float v, float* s_w) {
    int lane = threadIdx.x & 31, wid = threadIdx.x >> 5;
    float x = warpInclScan(v);
    if (lane == 31) s_w[wid] = x;
    __syncthreads();
    if (wid == 0) { float y = s_w[lane]; y = warpInclScan(y); s_w[lane] = y; }
    __syncthreads();
    float off = (wid > 0) ? s_w[wid - 1] : 0.0f;
    return x + off;
}

// inclusive block scan of two values sharing barriers
__device__ __forceinline__ void blockInclScan2(float& a, float& b, float* swa, float* swb) {
    int lane = threadIdx.x & 31, wid = threadIdx.x >> 5;
    float xa = warpInclScan(a), xb = warpInclScan(b);
    if (lane == 31) { swa[wid] = xa; swb[wid] = xb; }
    __syncthreads();
    if (wid == 0) {
        float ya = swa[lane], yb = swb[lane];
        ya = warpInclScan(ya); yb = warpInclScan(yb);
        swa[lane] = ya; swb[lane] = yb;
    }
    __syncthreads();
    a = xa + ((wid > 0) ? swa[wid - 1] : 0.0f);
    b = xb + ((wid > 0) ? swb[wid - 1] : 0.0f);
}

__device__ __forceinline__ float blockReduceMax(float v, float* s_red) {
    int t = threadIdx.x;
    #pragma unroll
    for (int o = 16; o > 0; o >>= 1) v = fmaxf(v, __shfl_xor_sync(0xffffffffu, v, o));
    if ((t & 31) == 0) s_red[t >> 5] = v;
    __syncthreads();
    if (t < 16) {
        float w = s_red[t];
        #pragma unroll
        for (int o = 8; o > 0; o >>= 1) w = fmaxf(w, __shfl_xor_sync(0xffffu, w, o));
        if (t == 0) s_red[0] = w;
    }
    __syncthreads();
    float r = s_red[0];
    __syncthreads();
    return r;
}

__device__ __forceinline__ float blockReduceSumF(float v, float* s_red) {
    int t = threadIdx.x;
    #pragma unroll
    for (int o = 16; o > 0; o >>= 1) v += __shfl_xor_sync(0xffffffffu, v, o);
    if ((t & 31) == 0) s_red[t >> 5] = v;
    __syncthreads();
    if (t < 16) {
        float w = s_red[t];
        #pragma unroll
        for (int o = 8; o > 0; o >>= 1) w += __shfl_xor_sync(0xffffu, w, o);
        if (t == 0) s_red[0] = w;
    }
    __syncthreads();
    float r = s_red[0];
    __syncthreads();
    return r;
}

__device__ __forceinline__ int blockReduceSumI(int v, int* s_red) {
    int t = threadIdx.x;
    #pragma unroll
    for (int o = 16; o > 0; o >>= 1) v += __shfl_xor_sync(0xffffffffu, v, o);
    if ((t & 31) == 0) s_red[t >> 5] = v;
    __syncthreads();
    if (t < 16) {
        int w = s_red[t];
        #pragma unroll
        for (int o = 8; o > 0; o >>= 1) w += __shfl_xor_sync(0xffffu, w, o);
        if (t == 0) s_red[0] = w;
    }
    __syncthreads();
    int r = s_red[0];
    __syncthreads();
    return r;
}

__device__ __forceinline__ void rotY(float qc, float qs, float wx, float wz,
                                     float& ox, float& oz) {
    // qvec = (0, -qs, 0); uv = cross(qvec, v); uuv = cross(qvec, uv)
    float uvx = (-qs) * wz;
    float uvz = qs * wx;
    float uuvx = (-qs) * uvz;
    float uuvz = qs * uvx;
    ox = wx + 2.0f * (qc * uvx + uuvx);
    oz = wz + 2.0f * (qc * uvz + uuvz);
}

// norms for one timestep tau given P(tau)..P(tau-3); guards by tau
__device__ __forceinline__ float energyTerm(int tau,
    float px, float py, float pz,
    float q1x, float q1y, float q1z,   // P(tau-1)
    float q2x, float q2y, float q2z,   // P(tau-2)
    float q3x, float q3y, float q3z)   // P(tau-3)
{
    float v3x = (tau >= 1) ? px - q1x : 0.f, v3y = (tau >= 1) ? py - q1y : 0.f, v3z = (tau >= 1) ? pz - q1z : 0.f;
    float v2x = (tau >= 2) ? q1x - q2x : 0.f, v2y = (tau >= 2) ? q1y - q2y : 0.f, v2z = (tau >= 2) ? q1z - q2z : 0.f;
    float v1x = (tau >= 3) ? q2x - q3x : 0.f, v1y = (tau >= 3) ? q2y - q3y : 0.f, v1z = (tau >= 3) ? q2z - q3z : 0.f;
    float a3x = (tau >= 1) ? v3x - v2x : 0.f, a3y = (tau >= 1) ? v3y - v2y : 0.f, a3z = (tau >= 1) ? v3z - v2z : 0.f;
    float a2x = (tau >= 2) ? v2x - v1x : 0.f, a2y = (tau >= 2) ? v2y - v1y : 0.f, a2z = (tau >= 2) ? v2z - v1z : 0.f;
    float jx  = (tau >= 1) ? a3x - a2x : 0.f, jy  = (tau >= 1) ? a3y - a2y : 0.f, jz  = (tau >= 1) ? a3z - a2z : 0.f;
    float nv = sqrtf(((v3x * v3x + v3y * v3y) + v3z * v3z) + 1e-12f);
    float na = sqrtf(((a3x * a3x + a3y * a3y) + a3z * a3z) + 1e-12f);
    float nj = sqrtf(((jx * jx + jy * jy) + jz * jz) + 1e-12f);
    return (nv + 0.6f * na) + 0.35f * nj;
}

__global__ __launch_bounds__(NT, 2)
void msal_kernel(const float* __restrict__ motion,
                 const int* __restrict__ mask,
                 float* __restrict__ out,
                 int Bn)
{
    __shared__ float s_rx[TT], s_rz[TT];
    __shared__ float s_px[2][TT], s_py[2][TT], s_pz[2][TT];
    __shared__ float s_sal[TT];
    __shared__ float s_srt[2][TT];
    __shared__ float s_redf[32];
    __shared__ int   s_redi[32];
    __shared__ float s_w1[32], s_w2[32];

    const int tid = threadIdx.x;
    const int b = blockIdx.x;
    const int t0 = 2 * tid, t1 = t0 + 1;
    const float* row0 = motion + ((long)b * TT + t0) * DD;
    const float* row1 = row0 + DD;
    const int mv0 = mask[(long)b * TT + t0];
    const int mv1 = mask[(long)b * TT + t1];
    const float mf0 = mv0 ? 1.0f : 0.0f;
    const float mf1 = mv1 ? 1.0f : 0.0f;

    // ---- ang: exclusive cumsum of rot_vel ----
    const float rv0 = row0[0], rv1 = row1[0];
    {
        float pair = rv0 + rv1;
        float incl = blockInclScan(pair, s_w1);
        float excl = incl - pair;
        s_w1[31] = excl;  // dummy keep-alive not needed; use locals below
    }
    // recompute (scan returns per-thread; need excl accessible)
    // NOTE: blockInclScan already returned; restructure: do it properly:
    float ang0, ang1;
    {
        // redo scan cleanly (previous block folded): compute again is wasteful; instead
        // we inline the value here. (This block intentionally empty.)
        ang0 = 0.f; ang1 = 0.f;
    }
    // --- proper single scan ---
    {
        __syncthreads();
        float pair = rv0 + rv1;
        float incl = blockInclScan(pair, s_w1);
        float excl = incl - pair;
        ang0 = excl;
        ang1 = excl + rv0;
    }
    const float qc0 = cosf(ang0), qs0 = sinf(ang0);
    const float qc1 = cosf(ang1), qs1 = sinf(ang1);

    // ---- root xz steps rotated, then inclusive cumsum ----
    float sx0 = 0.f, sz0 = 0.f, sx1, sz1;
    {
        float vx0 = 0.f, vz0 = 0.f;
        if (t0 > 0) { vx0 = row0[1 - DD]; vz0 = row0[2 - DD]; }
        float vx1 = row0[1], vz1 = row0[2];   // row of t1-1 = row0
        rotY(qc0, qs0, vx0, vz0, sx0, sz0);
        rotY(qc1, qs1, vx1, vz1, sx1, sz1);
    }
    float rx0, rz0, rx1, rz1;
    {
        float pairx = sx0 + sx1, pairz = sz0 + sz1;
        __syncthreads();   // protect s_w reuse
        float ix = pairx, iz = pairz;
        blockInclScan2(ix, iz, s_w1, s_w2);
        float ex = ix - pairx, ez = iz - pairz;
        rx0 = ex + sx0;        rz0 = ez + sz0;
        rx1 = (ex + sx0) + sx1; rz1 = (ez + sz0) + sz1;
    }
    s_rx[t0] = rx0; s_rx[t1] = rx1;
    s_rz[t0] = rz0; s_rz[t1] = rz1;
    // (joint-loop barrier below covers visibility before neighbor reads)

    // ---- group energies ----
    float S0a = 0.f, S1a = 0.f, S2a = 0.f, S3a = 0.f;   // timestep t0
    float S0b = 0.f, S1b = 0.f, S2b = 0.f, S3b = 0.f;   // timestep t1

    const float py0r = row0[3], py1r = row1[3];
    float wx0 = 0.f, wy0 = 0.f, wz0 = 0.f;
    float wx1 = 0.f, wy1 = 0.f, wz1 = 0.f;

    for (int j = 0; j < 22; j++) {
        const int buf = j & 1;
        float px0, py0, pz0, px1, py1, pz1;
        if (j == 0) {
            px0 = rx0; py0 = py0r; pz0 = rz0;
            px1 = rx1; py1 = py1r; pz1 = rz1;
        } else {
            float ax, az, bx, bz;
            rotY(qc0, qs0, wx0, wz0, ax, az);
            rotY(qc1, qs1, wx1, wz1, bx, bz);
            px0 = ax + rx0; py0 = wy0; pz0 = az + rz0;
            px1 = bx + rx1; py1 = wy1; pz1 = bz + rz1;
        }
        // prefetch next joint raw data
        float nx0 = 0.f, ny0 = 0.f, nz0 = 0.f, nx1 = 0.f, ny1 = 0.f, nz1 = 0.f;
        if (j < 21) {
            const int o = 4 + 3 * j;
            nx0 = row0[o]; ny0 = row0[o + 1]; nz0 = row0[o + 2];
            nx1 = row1[o]; ny1 = row1[o + 1]; nz1 = row1[o + 2];
        }
        s_px[buf][t0] = px0; s_py[buf][t0] = py0; s_pz[buf][t0] = pz0;
        s_px[buf][t1] = px1; s_py[buf][t1] = py1; s_pz[buf][t1] = pz1;
        __syncthreads();

        // neighbors: t0-1, t0-2, t0-3 from smem (guarded)
        float m1x = 0.f, m1y = 0.f, m1z = 0.f;
        float m2x = 0.f, m2y = 0.f, m2z = 0.f;
        float m3x = 0.f, m3y = 0.f, m3z = 0.f;
        if (t0 >= 1) { m1x = s_px[buf][t0-1]; m1y = s_py[buf][t0-1]; m1z = s_pz[buf][t0-1]; }
        if (t0 >= 2) { m2x = s_px[buf][t0-2]; m2y = s_py[buf][t0-2]; m2z = s_pz[buf][t0-2]; }
        if (t0 >= 3) { m3x = s_px[buf][t0-3]; m3y = s_py[buf][t0-3]; m3z = s_pz[buf][t0-3]; }

        float e0 = energyTerm(t0, px0, py0, pz0, m1x, m1y, m1z, m2x, m2y, m2z, m3x, m3y, m3z);
        float e1 = energyTerm(t1, px1, py1, pz1, px0, py0, pz0, m1x, m1y, m1z, m2x, m2y, m2z);

        int g = c_grp[j];
        if      (g == 0) { S0a += e0; S0b += e1; }
        else if (g == 1) { S1a += e0; S1b += e1; }
        else if (g == 2) { S2a += e0; S2b += e1; }
        else             { S3a += e0; S3b += e1; }

        wx0 = nx0; wy0 = ny0; wz0 = nz0;
        wx1 = nx1; wy1 = ny1; wz1 = nz1;
    }

    float Ea = (((1.6f * (S0a / 6.0f) + 1.4f * (S1a / 4.0f)) + 1.2f * (S2a / 8.0f)) + 0.8f * (S3a / 4.0f));
    float Eb = (((1.6f * (S0b / 6.0f) + 1.4f * (S1b / 4.0f)) + 1.2f * (S2b / 8.0f)) + 0.8f * (S3b / 4.0f));

    // ---- turning ----
    float turn0, turn1;
    {
        float pvx = 0.f, pvz = 0.f;
        if (t0 >= 1) { pvx = rx0 - s_rx[t0 - 1]; pvz = rz0 - s_rz[t0 - 1]; }
        bool z1 = (fabsf(pvx) < 1e-8f) && (fabsf(pvz) < 1e-8f);
        float h1 = atan2f(z1 ? 0.f : pvz, z1 ? 1.f : pvx);
        float h0 = 0.f;
        if (t0 >= 2) {
            float qx = s_rx[t0 - 1] - s_rx[t0 - 2];
            float qz = s_rz[t0 - 1] - s_rz[t0 - 2];
            bool z0 = (fabsf(qx) < 1e-8f) && (fabsf(qz) < 1e-8f);
            h0 = atan2f(z0 ? 0.f : qz, z0 ? 1.f : qx);
        }
        float hd = (t0 >= 1) ? h1 - h0 : 0.f;
        float wr = atan2f(sinf(hd), cosf(hd));
        turn0 = fabsf(wr) * sqrtf((pvx * pvx + pvz * pvz) + 1e-12f);
    }
    {
        float pvx = rx1 - rx0, pvz = rz1 - rz0;   // t1 >= 1 always
        bool z1 = (fabsf(pvx) < 1e-8f) && (fabsf(pvz) < 1e-8f);
        float h1 = atan2f(z1 ? 0.f : pvz, z1 ? 1.f : pvx);
        float h0 = 0.f;
        if (t1 >= 2) {
            float qx = rx0 - s_rx[t0 - 1];
            float qz = rz0 - s_rz[t0 - 1];
            bool z0 = (fabsf(qx) < 1e-8f) && (fabsf(qz) < 1e-8f);
            h0 = atan2f(z0 ? 0.f : qz, z0 ? 1.f : qx);
        }
        float hd = h1 - h0;
        float wr = atan2f(sinf(hd), cosf(hd));
        turn1 = fabsf(wr) * sqrtf((pvx * pvx + pvz * pvz) + 1e-12f);
    }

    float sal0 = (Ea + 1.6f * turn0) * mf0;
    float sal1 = (Eb + 1.6f * turn1) * mf1;

    // ---- normalize by row max ----
    float m = blockReduceMax(fmaxf(sal0, sal1), s_redf);
    m = fmaxf(m, 1e-6f);
    float salN0 = fminf(fmaxf(sal0 / m, 0.0f), 1.0f) * mf0;
    float salN1 = fminf(fmaxf(sal1 / m, 0.0f), 1.0f) * mf1;
    s_sal[t0] = salN0; s_sal[t1] = salN1;
    __syncthreads();

    // ---- local max suppression (window 5, pad 2) ----
    float lm0 = salN0, lm1 = salN1;
    #pragma unroll
    for (int d = -2; d <= 2; d++) {
        int i0 = t0 + d, i1 = t1 + d;
        if (i0 >= 0 && i0 < TT) lm0 = fmaxf(lm0, s_sal[i0]);
        if (i1 >= 0 && i1 < TT) lm1 = fmaxf(lm1, s_sal[i1]);
    }
    float probs0 = salN0 * ((salN0 >= lm0 - 1e-6f) ? 1.0f : 0.0f) * mf0;
    float probs1 = salN1 * ((salN1 >= lm1 - 1e-6f) ? 1.0f : 0.0f) * mf1;
    probs0 = fminf(fmaxf(probs0, 0.0f), 1.0f) * mf0;
    probs1 = fminf(fmaxf(probs1, 0.0f), 1.0f) * mf1;

    // ---- adaptive ST ----
    int n = blockReduceSumI((mv0 ? 1 : 0) + (mv1 ? 1 : 0), s_redi);
    float hv = (n > 0) ? 1.0f : 0.0f;
    int last = ((n > 1) ? n : 1) - 1;
    float ep0 = (t0 == 0 || t0 == last) ? hv : 0.0f;
    float ep1 = (t1 == 0 || t1 == last) ? hv : 0.0f;
    probs0 = fmaxf(probs0, ep0) * mf0;
    probs1 = fmaxf(probs1, ep1) * mf1;

    float nf = (float)((n > 1) ? n : 1);
    float asum = blockReduceSumF(probs0 * mf0 + probs1 * mf1, s_redf);
    float activity = asum / nf;
    float q = 0.85f + 0.1f * 0.5f - 0.1f * activity;
    q = fminf(fmaxf(q, 0.8f), 0.95f);
    float pos = q * (nf - 1.0f);
    float lof = floorf(pos), hif = ceilf(pos);
    int ilo = (int)lof, ihi = (int)hif;

    // ---- bitonic sort: 1024 elems, 2 per thread (i0=tid, i1=tid+512) ----
    const int i0 = tid, i1 = tid + NT;
    float v0 = mv0 ? probs0 : 2.0f;
    float v1 = mv1 ? probs1 : 2.0f;
    int pb = 0;
    for (int k = 2; k <= TT; k <<= 1) {
        bool up0 = ((i0 & k) == 0);
        bool up1 = ((i1 & k) == 0);
        int j2 = k >> 1;
        if (j2 == NT) {
            // partner pair is in-thread: i0 is lower (bit NT clear), i1 upper
            float mn = fminf(v0, v1), mx = fmaxf(v0, v1);
            v0 = up0 ? mn : mx;
            v1 = up0 ? mx : mn;
            j2 = NT >> 1;
        }
        for (; j2 >= 32; j2 >>= 1) {
            s_srt[pb][i0] = v0; s_srt[pb][i1] = v1;
            __syncthreads();
            float p0 = s_srt[pb][i0 ^ j2];
            float p1 = s_srt[pb][i1 ^ j2];
            pb ^= 1;
            bool l0 = (i0 & j2) == 0, l1 = (i1 & j2) == 0;
            v0 = (l0 == up0) ? fminf(v0, p0) : fmaxf(v0, p0);
            v1 = (l1 == up1) ? fminf(v1, p1) : fmaxf(v1, p1);
        }
        for (; j2 >= 1; j2 >>= 1) {
            float p0 = __shfl_xor_sync(0xffffffffu, v0, j2);
            float p1 = __shfl_xor_sync(0xffffffffu, v1, j2);
            bool l0 = (i0 & j2) == 0, l1 = (i1 & j2) == 0;
            v0 = (l0 == up0) ? fminf(v0, p0) : fmaxf(v0, p0);
            v1 = (l1 == up1) ? fminf(v1, p1) : fmaxf(v1, p1);
        }
    }
    s_srt[pb][i0] = v0; s_srt[pb][i1] = v1;
    __syncthreads();
    float vlo = s_srt[pb][ilo], vhi = s_srt[pb][ihi];
    float cut = vlo + (pos - lof) * (vhi - vlo);

    float hard0, hard1;
    if (n > 0 && n <= 2)      { hard0 = mf0; hard1 = mf1; }
    else if (n > 2)           { hard0 = (probs0 >= cut) ? 1.0f : 0.0f;
                                hard1 = (probs1 >= cut) ? 1.0f : 0.0f; }
    else                      { hard0 = 0.0f; hard1 = 0.0f; }

    hard0 = fmaxf(hard0, ep0) * mf0;
    hard1 = fmaxf(hard1, ep1) * mf1;
    float pF0 = fmaxf(probs0, ep0) * mf0;
    float pF1 = fmaxf(probs1, ep1) * mf1;
    float st0 = ((hard0 + pF0) - pF0) * mf0;
    float st1 = ((hard1 + pF1) - pF1) * mf1;

    out[(long)b * TT + t0] = pF0;
    out[(long)b * TT + t1] = pF1;
    out[(long)Bn * TT + (long)b * TT + t0] = st0;
    out[(long)Bn * TT + (long)b * TT + t1] = st1;
}

extern "C" void kernel_launch(void* const* d_in, const int* in_sizes, int n_in,
                              void* d_out, int out_size) {
    const float* motion = (const float*)d_in[0];
    const int* mask = (const int*)d_in[1];
    float* out = (float*)d_out;
    int Bn = in_sizes[0] / (TT * DD);
    msal_kernel<<<Bn, NT>>>(motion, mask, out, Bn);
}

// round 7
// speedup vs baseline: 2.1869x; 1.0932x over previous
#include <cuda_runtime.h>

#define TT 1024
#define NT 512
#define DD 263

// group id per joint: 0=ROOT_AND_SPINE(n=6), 1=FEET(n=4), 2=HANDS(n=8), 3=OTHER(n=4)
__constant__ int c_grp[22] = {0,3,3,0,3,3,0,1,1,0,1,1,0,2,2,0,2,2,2,2,2,2};

__device__ __forceinline__ float warpInclScan(float v) {
    int lane = threadIdx.x & 31;
    #pragma unroll
    for (int o = 1; o < 32; o <<= 1) {
        float n = __shfl_up_sync(0xffffffffu, v, o);
        if (lane >= o) v += n;
    }
    return v;
}

__device__ __forceinline__ float blockInclScan(float v, float* s_w) {
    int lane = threadIdx.x & 31, wid = threadIdx.x >> 5;
    float x = warpInclScan(v);
    if (lane == 31) s_w[wid] = x;
    __syncthreads();
    if (wid == 0) { float y = s_w[lane]; y = warpInclScan(y); s_w[lane] = y; }
    __syncthreads();
    float off = (wid > 0) ? s_w[wid - 1] : 0.0f;
    return x + off;
}

__device__ __forceinline__ void blockInclScan2(float& a, float& b, float* swa, float* swb) {
    int lane = threadIdx.x & 31, wid = threadIdx.x >> 5;
    float xa = warpInclScan(a), xb = warpInclScan(b);
    if (lane == 31) { swa[wid] = xa; swb[wid] = xb; }
    __syncthreads();
    if (wid == 0) {
        float ya = swa[lane], yb = swb[lane];
        ya = warpInclScan(ya); yb = warpInclScan(yb);
        swa[lane] = ya; swb[lane] = yb;
    }
    __syncthreads();
    a = xa + ((wid > 0) ? swa[wid - 1] : 0.0f);
    b = xb + ((wid > 0) ? swb[wid - 1] : 0.0f);
}

__device__ __forceinline__ float blockReduceMax(float v, float* s_red) {
    int t = threadIdx.x;
    #pragma unroll
    for (int o = 16; o > 0; o >>= 1) v = fmaxf(v, __shfl_xor_sync(0xffffffffu, v, o));
    if ((t & 31) == 0) s_red[t >> 5] = v;
    __syncthreads();
    if (t < 16) {
        float w = s_red[t];
        #pragma unroll
        for (int o = 8; o > 0; o >>= 1) w = fmaxf(w, __shfl_xor_sync(0xffffu, w, o));
        if (t == 0) s_red[0] = w;
    }
    __syncthreads();
    float r = s_red[0];
    __syncthreads();
    return r;
}

__device__ __forceinline__ float blockReduceSumF(float v, float* s_red) {
    int t = threadIdx.x;
    #pragma unroll
    for (int o = 16; o > 0; o >>= 1) v += __shfl_xor_sync(0xffffffffu, v, o);
    if ((t & 31) == 0) s_red[t >> 5] = v;
    __syncthreads();
    if (t < 16) {
        float w = s_red[t];
        #pragma unroll
        for (int o = 8; o > 0; o >>= 1) w += __shfl_xor_sync(0xffffu, w, o);
        if (t == 0) s_red[0] = w;
    }
    __syncthreads();
    float r = s_red[0];
    __syncthreads();
    return r;
}

__device__ __forceinline__ int blockReduceSumI(int v, int* s_red) {
    int t = threadIdx.x;
    #pragma unroll
    for (int o = 16; o > 0; o >>= 1) v += __shfl_xor_sync(0xffffffffu, v, o);
    if ((t & 31) == 0) s_red[t >> 5] = v;
    __syncthreads();
    if (t < 16) {
        int w = s_red[t];
        #pragma unroll
        for (int o = 8; o > 0; o >>= 1) w += __shfl_xor_sync(0xffffu, w, o);
        if (t == 0) s_red[0] = w;
    }
    __syncthreads();
    int r = s_red[0];
    __syncthreads();
    return r;
}

__device__ __forceinline__ void rotY(float qc, float qs, float wx, float wz,
                                     float& ox, float& oz) {
    float uvx = (-qs) * wz;
    float uvz = qs * wx;
    float uuvx = (-qs) * uvz;
    float uuvz = qs * uvx;
    ox = wx + 2.0f * (qc * uvx + uuvx);
    oz = wz + 2.0f * (qc * uvz + uuvz);
}

// unguarded energy term (valid when tau >= 3)
__device__ __forceinline__ float energyFast(
    float px, float py, float pz,
    float q1x, float q1y, float q1z,
    float q2x, float q2y, float q2z,
    float q3x, float q3y, float q3z)
{
    float v3x = px - q1x,  v3y = py - q1y,  v3z = pz - q1z;
    float v2x = q1x - q2x, v2y = q1y - q2y, v2z = q1z - q2z;
    float v1x = q2x - q3x, v1y = q2y - q3y, v1z = q2z - q3z;
    float a3x = v3x - v2x, a3y = v3y - v2y, a3z = v3z - v2z;
    float a2x = v2x - v1x, a2y = v2y - v1y, a2z = v2z - v1z;
    float jx  = a3x - a2x, jy  = a3y - a2y, jz  = a3z - a2z;
    float nv = sqrtf(((v3x * v3x + v3y * v3y) + v3z * v3z) + 1e-12f);
    float na = sqrtf(((a3x * a3x + a3y * a3y) + a3z * a3z) + 1e-12f);
    float nj = sqrtf(((jx * jx + jy * jy) + jz * jz) + 1e-12f);
    return (nv + 0.6f * na) + 0.35f * nj;
}

// guarded energy term (edge timesteps)
__device__ __forceinline__ float energyGuard(int tau,
    float px, float py, float pz,
    float q1x, float q1y, float q1z,
    float q2x, float q2y, float q2z,
    float q3x, float q3y, float q3z)
{
    float v3x = (tau >= 1) ? px - q1x : 0.f, v3y = (tau >= 1) ? py - q1y : 0.f, v3z = (tau >= 1) ? pz - q1z : 0.f;
    float v2x = (tau >= 2) ? q1x - q2x : 0.f, v2y = (tau >= 2) ? q1y - q2y : 0.f, v2z = (tau >= 2) ? q1z - q2z : 0.f;
    float v1x = (tau >= 3) ? q2x - q3x : 0.f, v1y = (tau >= 3) ? q2y - q3y : 0.f, v1z = (tau >= 3) ? q2z - q3z : 0.f;
    float a3x = (tau >= 1) ? v3x - v2x : 0.f, a3y = (tau >= 1) ? v3y - v2y : 0.f, a3z = (tau >= 1) ? v3z - v2z : 0.f;
    float a2x = (tau >= 2) ? v2x - v1x : 0.f, a2y = (tau >= 2) ? v2y - v1y : 0.f, a2z = (tau >= 2) ? v2z - v1z : 0.f;
    float jx  = (tau >= 1) ? a3x - a2x : 0.f, jy  = (tau >= 1) ? a3y - a2y : 0.f, jz  = (tau >= 1) ? a3z - a2z : 0.f;
    float nv = sqrtf(((v3x * v3x + v3y * v3y) + v3z * v3z) + 1e-12f);
    float na = sqrtf(((a3x * a3x + a3y * a3y) + a3z * a3z) + 1e-12f);
    float nj = sqrtf(((jx * jx + jy * jy) + jz * jz) + 1e-12f);
    return (nv + 0.6f * na) + 0.35f * nj;
}

__device__ __forceinline__ float wrapPi(float hd) {
    const float TWO_PI = 6.28318530717958647692f;
    const float INV_TWO_PI = 0.15915494309189533577f;
    return hd - TWO_PI * rintf(hd * INV_TWO_PI);
}

__global__ __launch_bounds__(NT, 2)
void msal_kernel(const float* __restrict__ motion,
                 const int* __restrict__ mask,
                 float* __restrict__ out,
                 int Bn)
{
    __shared__ float2 s_px[2][NT], s_py[2][NT], s_pz[2][NT]; // {val(t0), val(t1)} per pair
    __shared__ float4 s_rth[NT];                              // {rx1, rz1, h1, pad}
    __shared__ float2 s_sal[NT];
    __shared__ float  s_srt[2][TT];
    __shared__ float  s_redf[32];
    __shared__ int    s_redi[32];
    __shared__ float  s_w1[32], s_w2[32];

    const int tid = threadIdx.x;
    const int b = blockIdx.x;
    const int t0 = 2 * tid, t1 = t0 + 1;
    const float* row0 = motion + ((long)b * TT + t0) * DD;
    const float* row1 = row0 + DD;
    const int2 mvp = ((const int2*)(mask + (long)b * TT))[tid];
    const int mv0 = mvp.x, mv1 = mvp.y;
    const float mf0 = mv0 ? 1.0f : 0.0f;
    const float mf1 = mv1 ? 1.0f : 0.0f;

    // ---- ang: exclusive cumsum of rot_vel ----
    const float rv0 = row0[0], rv1 = row1[0];
    float ang0, ang1;
    {
        float pair = rv0 + rv1;
        float incl = blockInclScan(pair, s_w1);
        float excl = incl - pair;
        ang0 = excl;
        ang1 = excl + rv0;
    }
    const float qc0 = cosf(ang0), qs0 = sinf(ang0);
    const float qc1 = cosf(ang1), qs1 = sinf(ang1);

    // ---- root xz steps rotated, then inclusive cumsum ----
    float sx0 = 0.f, sz0 = 0.f, sx1, sz1;
    {
        float vx0 = 0.f, vz0 = 0.f;
        if (t0 > 0) { vx0 = row0[1 - DD]; vz0 = row0[2 - DD]; }
        float vx1 = row0[1], vz1 = row0[2];
        rotY(qc0, qs0, vx0, vz0, sx0, sz0);
        rotY(qc1, qs1, vx1, vz1, sx1, sz1);
    }
    float rx0, rz0, rx1, rz1;
    {
        float pairx = sx0 + sx1, pairz = sz0 + sz1;
        __syncthreads();   // protect s_w reuse
        float ix = pairx, iz = pairz;
        blockInclScan2(ix, iz, s_w1, s_w2);
        float ex = ix - pairx, ez = iz - pairz;
        rx0 = ex + sx0;         rz0 = ez + sz0;
        rx1 = (ex + sx0) + sx1; rz1 = (ez + sz0) + sz1;
    }

    // heading(t1) computed in-thread; stash root(t1) + h1 for neighbor use.
    float h_t1;
    {
        float pv1x = rx1 - rx0, pv1z = rz1 - rz0;
        bool z = (fabsf(pv1x) < 1e-8f) && (fabsf(pv1z) < 1e-8f);
        h_t1 = atan2f(z ? 0.f : pv1z, z ? 1.f : pv1x);
    }
    s_rth[tid] = make_float4(rx1, rz1, h_t1, 0.f);
    // visibility covered by joint-loop barriers below; read only after loop.

    // ---- group energies ----
    float S0a = 0.f, S1a = 0.f, S2a = 0.f, S3a = 0.f;
    float S0b = 0.f, S1b = 0.f, S2b = 0.f, S3b = 0.f;

    const float py0r = row0[3], py1r = row1[3];
    float wx0 = 0.f, wy0 = 0.f, wz0 = 0.f;
    float wx1 = 0.f, wy1 = 0.f, wz1 = 0.f;

    for (int j = 0; j < 22; j++) {
        const int buf = j & 1;
        float px0, py0, pz0, px1, py1, pz1;
        if (j == 0) {
            px0 = rx0; py0 = py0r; pz0 = rz0;
            px1 = rx1; py1 = py1r; pz1 = rz1;
        } else {
            float ax, az, bx, bz;
            rotY(qc0, qs0, wx0, wz0, ax, az);
            rotY(qc1, qs1, wx1, wz1, bx, bz);
            px0 = ax + rx0; py0 = wy0; pz0 = az + rz0;
            px1 = bx + rx1; py1 = wy1; pz1 = bz + rz1;
        }
        // prefetch next joint raw data
        float nx0 = 0.f, ny0 = 0.f, nz0 = 0.f, nx1 = 0.f, ny1 = 0.f, nz1 = 0.f;
        if (j < 21) {
            const int o = 4 + 3 * j;
            nx0 = row0[o]; ny0 = row0[o + 1]; nz0 = row0[o + 2];
            nx1 = row1[o]; ny1 = row1[o + 1]; nz1 = row1[o + 2];
        }
        s_px[buf][tid] = make_float2(px0, px1);
        s_py[buf][tid] = make_float2(py0, py1);
        s_pz[buf][tid] = make_float2(pz0, pz1);
        __syncthreads();

        float e0, e1;
        if (tid >= 2) {
            // A = pair tid-1 = {P(t0-2), P(t0-1)}; B = pair tid-2 = {P(t0-4), P(t0-3)}
            float2 Ax = s_px[buf][tid - 1], Ay = s_py[buf][tid - 1], Az = s_pz[buf][tid - 1];
            float2 Bx = s_px[buf][tid - 2], By = s_py[buf][tid - 2], Bz = s_pz[buf][tid - 2];
            e0 = energyFast(px0, py0, pz0,
                            Ax.y, Ay.y, Az.y,
                            Ax.x, Ay.x, Az.x,
                            Bx.y, By.y, Bz.y);
            e1 = energyFast(px1, py1, pz1,
                            px0, py0, pz0,
                            Ax.y, Ay.y, Az.y,
                            Ax.x, Ay.x, Az.x);
        } else {
            float2 Ax = make_float2(0.f, 0.f), Ay = Ax, Az = Ax;
            if (tid >= 1) { Ax = s_px[buf][tid - 1]; Ay = s_py[buf][tid - 1]; Az = s_pz[buf][tid - 1]; }
            e0 = energyGuard(t0, px0, py0, pz0,
                             Ax.y, Ay.y, Az.y,
                             Ax.x, Ay.x, Az.x,
                             0.f, 0.f, 0.f);
            e1 = energyGuard(t1, px1, py1, pz1,
                             px0, py0, pz0,
                             Ax.y, Ay.y, Az.y,
                             Ax.x, Ay.x, Az.x);
        }

        int g = c_grp[j];
        if      (g == 0) { S0a += e0; S0b += e1; }
        else if (g == 1) { S1a += e0; S1b += e1; }
        else if (g == 2) { S2a += e0; S2b += e1; }
        else             { S3a += e0; S3b += e1; }

        wx0 = nx0; wy0 = ny0; wz0 = nz0;
        wx1 = nx1; wy1 = ny1; wz1 = nz1;
    }

    float Ea = (((1.6f * (S0a / 6.0f) + 1.4f * (S1a / 4.0f)) + 1.2f * (S2a / 8.0f)) + 0.8f * (S3a / 4.0f));
    float Eb = (((1.6f * (S0b / 6.0f) + 1.4f * (S1b / 4.0f)) + 1.2f * (S2b / 8.0f)) + 0.8f * (S3b / 4.0f));

    // ---- turning (2 atan2 per thread; heading(t0-1) from neighbor) ----
    float turn0, turn1;
    {
        float rxm1 = 0.f, rzm1 = 0.f, hprev = 0.f;
        if (tid >= 1) {
            float4 rr = s_rth[tid - 1];
            rxm1 = rr.x; rzm1 = rr.y; hprev = rr.z;
        }
        float pv0x = (tid >= 1) ? rx0 - rxm1 : 0.f;
        float pv0z = (tid >= 1) ? rz0 - rzm1 : 0.f;
        bool z = (fabsf(pv0x) < 1e-8f) && (fabsf(pv0z) < 1e-8f);
        float h_t0 = atan2f(z ? 0.f : pv0z, z ? 1.f : pv0x);
        float hd0 = (tid >= 1) ? h_t0 - hprev : 0.f;
        float hd1 = h_t1 - h_t0;
        float wr0 = wrapPi(hd0);
        float wr1 = wrapPi(hd1);
        float pv1x = rx1 - rx0, pv1z = rz1 - rz0;
        turn0 = fabsf(wr0) * sqrtf((pv0x * pv0x + pv0z * pv0z) + 1e-12f);
        turn1 = fabsf(wr1) * sqrtf((pv1x * pv1x + pv1z * pv1z) + 1e-12f);
    }

    float sal0 = (Ea + 1.6f * turn0) * mf0;
    float sal1 = (Eb + 1.6f * turn1) * mf1;

    // ---- normalize by row max ----
    float m = blockReduceMax(fmaxf(sal0, sal1), s_redf);
    m = fmaxf(m, 1e-6f);
    float salN0 = fminf(fmaxf(sal0 / m, 0.0f), 1.0f) * mf0;
    float salN1 = fminf(fmaxf(sal1 / m, 0.0f), 1.0f) * mf1;
    s_sal[tid] = make_float2(salN0, salN1);
    __syncthreads();

    // ---- local max suppression (window 5, pad 2) ----
    float2 L = (tid >= 1)      ? s_sal[tid - 1] : make_float2(-1.f, -1.f);
    float2 R = (tid < NT - 1)  ? s_sal[tid + 1] : make_float2(-1.f, -1.f);
    float lm0 = fmaxf(fmaxf(fmaxf(L.x, L.y), fmaxf(salN0, salN1)), R.x);
    float lm1 = fmaxf(fmaxf(fmaxf(L.y, salN0), fmaxf(salN1, R.x)), R.y);
    float probs0 = salN0 * ((salN0 >= lm0 - 1e-6f) ? 1.0f : 0.0f) * mf0;
    float probs1 = salN1 * ((salN1 >= lm1 - 1e-6f) ? 1.0f : 0.0f) * mf1;
    probs0 = fminf(fmaxf(probs0, 0.0f), 1.0f) * mf0;
    probs1 = fminf(fmaxf(probs1, 0.0f), 1.0f) * mf1;

    // ---- adaptive ST ----
    int n = blockReduceSumI((mv0 ? 1 : 0) + (mv1 ? 1 : 0), s_redi);
    float hv = (n > 0) ? 1.0f : 0.0f;
    int last = ((n > 1) ? n : 1) - 1;
    float ep0 = (t0 == 0 || t0 == last) ? hv : 0.0f;
    float ep1 = (t1 == last) ? hv : 0.0f;
    probs0 = fmaxf(probs0, ep0) * mf0;
    probs1 = fmaxf(probs1, ep1) * mf1;

    float nf = (float)((n > 1) ? n : 1);
    float asum = blockReduceSumF(probs0 * mf0 + probs1 * mf1, s_redf);
    float activity = asum / nf;
    float q = 0.85f + 0.1f * 0.5f - 0.1f * activity;
    q = fminf(fmaxf(q, 0.8f), 0.95f);
    float pos = q * (nf - 1.0f);
    float lof = floorf(pos), hif = ceilf(pos);
    int ilo = (int)lof, ihi = (int)hif;

    // ---- bitonic sort: 1024 elems, 2 per thread (i0=tid, i1=tid+512) ----
    const int i0 = tid, i1 = tid + NT;
    float v0 = mv0 ? probs0 : 2.0f;
    float v1 = mv1 ? probs1 : 2.0f;
    int pb = 0;
    for (int k = 2; k <= TT; k <<= 1) {
        bool up0 = ((i0 & k) == 0);
        bool up1 = ((i1 & k) == 0);
        int j2 = k >> 1;
        if (j2 == NT) {
            float mn = fminf(v0, v1), mx = fmaxf(v0, v1);
            v0 = up0 ? mn : mx;
            v1 = up0 ? mx : mn;
            j2 = NT >> 1;
        }
        for (; j2 >= 32; j2 >>= 1) {
            s_srt[pb][i0] = v0; s_srt[pb][i1] = v1;
            __syncthreads();
            float p0 = s_srt[pb][i0 ^ j2];
            float p1 = s_srt[pb][i1 ^ j2];
            pb ^= 1;
            bool l0 = (i0 & j2) == 0, l1 = (i1 & j2) == 0;
            v0 = (l0 == up0) ? fminf(v0, p0) : fmaxf(v0, p0);
            v1 = (l1 == up1) ? fminf(v1, p1) : fmaxf(v1, p1);
        }
        for (; j2 >= 1; j2 >>= 1) {
            float p0 = __shfl_xor_sync(0xffffffffu, v0, j2);
            float p1 = __shfl_xor_sync(0xffffffffu, v1, j2);
            bool l0 = (i0 & j2) == 0, l1 = (i1 & j2) == 0;
            v0 = (l0 == up0) ? fminf(v0, p0) : fmaxf(v0, p0);
            v1 = (l1 == up1) ? fminf(v1, p1) : fmaxf(v1, p1);
        }
    }
    s_srt[pb][i0] = v0; s_srt[pb][i1] = v1;
    __syncthreads();
    float vlo = s_srt[pb][ilo], vhi = s_srt[pb][ihi];
    float cut = vlo + (pos - lof) * (vhi - vlo);

    float hard0, hard1;
    if (n > 0 && n <= 2)      { hard0 = mf0; hard1 = mf1; }
    else if (n > 2)           { hard0 = (probs0 >= cut) ? 1.0f : 0.0f;
                                hard1 = (probs1 >= cut) ? 1.0f : 0.0f; }
    else                      { hard0 = 0.0f; hard1 = 0.0f; }

    hard0 = fmaxf(hard0, ep0) * mf0;
    hard1 = fmaxf(hard1, ep1) * mf1;
    float pF0 = fmaxf(probs0, ep0) * mf0;
    float pF1 = fmaxf(probs1, ep1) * mf1;
    float st0 = ((hard0 + pF0) - pF0) * mf0;
    float st1 = ((hard1 + pF1) - pF1) * mf1;

    ((float2*)(out + (long)b * TT))[tid] = make_float2(pF0, pF1);
    ((float2*)(out + (long)Bn * TT + (long)b * TT))[tid] = make_float2(st0, st1);
}

extern "C" void kernel_launch(void* const* d_in, const int* in_sizes, int n_in,
                              void* d_out, int out_size) {
    const float* motion = (const float*)d_in[0];
    const int* mask = (const int*)d_in[1];
    float* out = (float*)d_out;
    int Bn = in_sizes[0] / (TT * DD);
    msal_kernel<<<Bn, NT>>>(motion, mask, out, Bn);
}